// round 3
// baseline (speedup 1.0000x reference)
#include <cuda_runtime.h>

// TropicalLeNet, 3 stage-matched kernels, instruction-count-driven layout.

#define BMAX 256

__device__ float g_p1[BMAX * 6 * 14 * 14];  // conv1+pool output
__device__ float g_p2[BMAX * 400];          // conv2+pool output (o*25+i*5+j)

// ---------------------------------------------------------------------------
// Kernel A: min-plus conv1 (C=1 -> O=6, k=5, pad=2) + 2x2 avgpool.
// grid (2, B): CTA handles 3 output channels of one image. 224 threads,
// 196 active in compute; window regs amortized over 3 channels.
// ---------------------------------------------------------------------------
__global__ void __launch_bounds__(224, 2)
conv1_kernel(const float* __restrict__ input, const float* __restrict__ w1)
{
    const int cg = blockIdx.x, b = blockIdx.y;   // channel group: 3*cg..3*cg+2
    const int tid = threadIdx.x;

    __shared__ float xp[32 * 33];   // zero-padded input, row stride 33
    __shared__ float ws[75];

    for (int i = tid; i < 32 * 33; i += 224) xp[i] = 0.0f;
    if (tid < 75) ws[tid] = w1[cg * 75 + tid];
    __syncthreads();

    const float* inb = input + b * 784;
    for (int i = tid; i < 784; i += 224) {
        int h = i / 28, w = i % 28;
        xp[(h + 2) * 33 + (w + 2)] = inb[i];
    }
    __syncthreads();

    if (tid < 196) {
        const int i = tid / 14, j = tid % 14;

        float win[6][6];
        #pragma unroll
        for (int u = 0; u < 6; u++)
            #pragma unroll
            for (int v = 0; v < 6; v++)
                win[u][v] = xp[(2 * i + u) * 33 + (2 * j + v)];

        #pragma unroll 1
        for (int cc = 0; cc < 3; cc++) {
            float wr[25];
            #pragma unroll
            for (int t = 0; t < 25; t++) wr[t] = ws[cc * 25 + t];  // broadcast

            float acc = 0.0f;
            #pragma unroll
            for (int u = 0; u < 2; u++)
            #pragma unroll
            for (int v = 0; v < 2; v++) {
                float m = win[u][v] + wr[0];
                #pragma unroll
                for (int t = 1; t < 25; t++)
                    m = fminf(m, win[u + t / 5][v + t % 5] + wr[t]);
                acc += m;
            }
            g_p1[(b * 6 + 3 * cg + cc) * 196 + tid] = 0.25f * acc;
        }
    }
}

// ---------------------------------------------------------------------------
// Kernel B: max-plus conv2 (C=6 -> O=16, k=5) + 2x2 avgpool.
// grid B: one CTA per image, 224 threads (200 active).
// thread = (ocp 0..7, spatial 0..24), computes output channels ocp and ocp+8;
// the 6x6 window (per input channel) is shared between the two channels.
// ---------------------------------------------------------------------------
__global__ void __launch_bounds__(224, 2)
conv2_kernel(const float* __restrict__ w2)
{
    const int b = blockIdx.x;
    const int tid = threadIdx.x;

    __shared__ float p1s[6 * 14 * 14];  // 1176
    __shared__ float ws[16 * 6 * 25];   // 2400

    const float* p1b = g_p1 + b * 1176;
    for (int i = tid; i < 1176; i += 224) p1s[i] = p1b[i];
    for (int i = tid; i < 2400; i += 224) ws[i]  = w2[i];
    __syncthreads();

    if (tid < 200) {
        const int ocp = tid / 25;        // 0..7
        const int sp  = tid % 25;
        const int i = sp / 5, j = sp % 5;

        float acc0 = 0.0f, acc1 = 0.0f;
        #pragma unroll 1
        for (int c = 0; c < 6; c++) {
            float win[6][6];
            #pragma unroll
            for (int u = 0; u < 6; u++)
                #pragma unroll
                for (int v = 0; v < 6; v++)
                    win[u][v] = p1s[c * 196 + (2 * i + u) * 14 + (2 * j + v)];

            float wr0[25], wr1[25];
            #pragma unroll
            for (int t = 0; t < 25; t++) {
                wr0[t] = ws[(ocp * 6 + c) * 25 + t];
                wr1[t] = ws[((ocp + 8) * 6 + c) * 25 + t];
            }

            #pragma unroll
            for (int u = 0; u < 2; u++)
            #pragma unroll
            for (int v = 0; v < 2; v++) {
                float m0 = win[u][v] + wr0[0];
                float m1 = win[u][v] + wr1[0];
                #pragma unroll
                for (int t = 1; t < 25; t++) {
                    float xv = win[u + t / 5][v + t % 5];
                    m0 = fmaxf(m0, xv + wr0[t]);
                    m1 = fmaxf(m1, xv + wr1[t]);
                }
                acc0 += m0;
                acc1 += m1;
            }
        }
        g_p2[b * 400 + ocp * 25 + sp]       = 0.25f * acc0;
        g_p2[b * 400 + (ocp + 8) * 25 + sp] = 0.25f * acc1;
    }
}

// ---------------------------------------------------------------------------
// Kernel C: FC stack. grid B/2: two images per CTA (halves fw1 L2 traffic),
// 256 threads = 8 warps; warp parity selects image, warp computes 2 outputs.
// ---------------------------------------------------------------------------
__global__ void __launch_bounds__(256)
fc_kernel(const float* __restrict__ fw1, const float* __restrict__ fb1,
          const float* __restrict__ fw2, const float* __restrict__ fb2,
          const float* __restrict__ fw3, const float* __restrict__ fb3,
          float* __restrict__ out)
{
    const int bg = blockIdx.x;           // image pair
    const int tid = threadIdx.x;
    const int warp = tid >> 5, lane = tid & 31;

    __shared__ float x[2][400];
    __shared__ float h1[2][120];
    __shared__ float h2[2][84];

    for (int i = tid; i < 800; i += 256)
        x[i / 400][i % 400] = g_p2[bg * 800 + i];
    __syncthreads();

    // fc1: 400 -> 120, relu. 120 tasks = (img, out-pair).
    for (int t = warp; t < 120; t += 8) {
        const int img = t & 1, oo = t >> 1;
        const int o0 = 2 * oo, o1 = o0 + 1;
        const float* wa = fw1 + o0 * 400;
        const float* wb = fw1 + o1 * 400;
        const float* xv = x[img];
        float sa = 0.0f, sb = 0.0f;
        #pragma unroll 4
        for (int i = lane; i < 400; i += 32) {
            float v = xv[i];
            sa += v * wa[i];
            sb += v * wb[i];
        }
        #pragma unroll
        for (int off = 16; off; off >>= 1) {
            sa += __shfl_xor_sync(0xffffffffu, sa, off);
            sb += __shfl_xor_sync(0xffffffffu, sb, off);
        }
        if (lane == 0) {
            h1[img][o0] = fmaxf(sa + fb1[o0], 0.0f);
            h1[img][o1] = fmaxf(sb + fb1[o1], 0.0f);
        }
    }
    __syncthreads();

    // fc2: 120 -> 84, relu. 84 tasks.
    for (int t = warp; t < 84; t += 8) {
        const int img = t & 1, oo = t >> 1;
        const int o0 = 2 * oo, o1 = o0 + 1;
        const float* wa = fw2 + o0 * 120;
        const float* wb = fw2 + o1 * 120;
        const float* xv = h1[img];
        float sa = 0.0f, sb = 0.0f;
        #pragma unroll
        for (int i = lane; i < 120; i += 32) {
            float v = xv[i];
            sa += v * wa[i];
            sb += v * wb[i];
        }
        #pragma unroll
        for (int off = 16; off; off >>= 1) {
            sa += __shfl_xor_sync(0xffffffffu, sa, off);
            sb += __shfl_xor_sync(0xffffffffu, sb, off);
        }
        if (lane == 0) {
            h2[img][o0] = fmaxf(sa + fb2[o0], 0.0f);
            h2[img][o1] = fmaxf(sb + fb2[o1], 0.0f);
        }
    }
    __syncthreads();

    // fc3: 84 -> 10. 20 tasks = (img, out).
    for (int t = warp; t < 20; t += 8) {
        const int img = t & 1, o = t >> 1;
        const float* wrow = fw3 + o * 84;
        const float* xv = h2[img];
        float s = 0.0f;
        #pragma unroll
        for (int i = lane; i < 84; i += 32) s += xv[i] * wrow[i];
        #pragma unroll
        for (int off = 16; off; off >>= 1) s += __shfl_xor_sync(0xffffffffu, s, off);
        if (lane == 0) out[(2 * bg + img) * 10 + o] = s + fb3[o];
    }
}

extern "C" void kernel_launch(void* const* d_in, const int* in_sizes, int n_in,
                              void* d_out, int out_size)
{
    const float* input = (const float*)d_in[0];
    const float* w1    = (const float*)d_in[1];
    const float* w2    = (const float*)d_in[2];
    const float* fw1   = (const float*)d_in[3];
    const float* fb1   = (const float*)d_in[4];
    const float* fw2   = (const float*)d_in[5];
    const float* fb2   = (const float*)d_in[6];
    const float* fw3   = (const float*)d_in[7];
    const float* fb3   = (const float*)d_in[8];

    const int B = in_sizes[0] / 784;  // 256

    conv1_kernel<<<dim3(2, B), 224>>>(input, w1);
    conv2_kernel<<<B, 224>>>(w2);
    fc_kernel<<<B / 2, 256>>>(fw1, fb1, fw2, fb2, fw3, fb3, (float*)d_out);
}

// round 4
// speedup vs baseline: 1.1722x; 1.1722x over previous
#include <cuda_runtime.h>

// TropicalLeNet, 3 kernels. Instruction-mix optimized: aligned smem layouts,
// vectorized LDS/LDG, interleaved min/max chains.

#define BMAX 256

__device__ float g_p1[BMAX * 6 * 14 * 16];  // conv1+pool out, [b][c][14][16] (cols 14-15 unused)
__device__ float g_p2[BMAX * 400];          // conv2+pool out, [b][oc*25+sp]

// ---------------------------------------------------------------------------
// Kernel A: min-plus conv1 (C=1 -> O=6, k=5, pad=2) + 2x2 avgpool.
// grid (2, B): CTA = 3 output channels of one image. 224 threads, 196 active.
// Padded input is exactly 32x32 (row = 128B): windows load as LDS.64.
// ---------------------------------------------------------------------------
__global__ void __launch_bounds__(224)
conv1_kernel(const float* __restrict__ input, const float* __restrict__ w1)
{
    const int cg = blockIdx.x, b = blockIdx.y;   // channels 3*cg .. 3*cg+2
    const int tid = threadIdx.x;

    __shared__ __align__(16) float xp[32 * 32];
    __shared__ __align__(16) float ws[3 * 28];   // filters padded to 28 floats

    for (int i = tid; i < 1024; i += 224) xp[i] = 0.0f;
    if (tid < 75) ws[(tid / 25) * 28 + tid % 25] = w1[cg * 75 + tid];
    __syncthreads();

    const float* inb = input + b * 784;
    for (int i = tid; i < 784; i += 224) {
        int h = i / 28, w = i % 28;
        xp[(h + 2) * 32 + (w + 2)] = inb[i];
    }
    __syncthreads();

    if (tid < 196) {
        const int i = tid / 14, j = tid % 14;
        const int base = i * 64 + 2 * j;          // (2i)*32 + 2j, even -> 8B aligned

        float win[6][6];
        #pragma unroll
        for (int u = 0; u < 6; u++) {
            const float2* r = (const float2*)&xp[base + u * 32];
            float2 a = r[0], bb = r[1], c2 = r[2];
            win[u][0] = a.x;  win[u][1] = a.y;
            win[u][2] = bb.x; win[u][3] = bb.y;
            win[u][4] = c2.x; win[u][5] = c2.y;
        }

        #pragma unroll 1
        for (int cc = 0; cc < 3; cc++) {
            float wr[25];
            {
                const float4* wq = (const float4*)&ws[cc * 28];
                #pragma unroll
                for (int q = 0; q < 6; q++) {
                    float4 v = wq[q];
                    wr[4 * q]     = v.x; wr[4 * q + 1] = v.y;
                    wr[4 * q + 2] = v.z; wr[4 * q + 3] = v.w;
                }
                wr[24] = ws[cc * 28 + 24];
            }

            float m00 = win[0][0] + wr[0];
            float m01 = win[0][1] + wr[0];
            float m10 = win[1][0] + wr[0];
            float m11 = win[1][1] + wr[0];
            #pragma unroll
            for (int t = 1; t < 25; t++) {
                const int du = t / 5, dv = t % 5;
                const float w = wr[t];
                m00 = fminf(m00, win[du][dv]         + w);
                m01 = fminf(m01, win[du][dv + 1]     + w);
                m10 = fminf(m10, win[du + 1][dv]     + w);
                m11 = fminf(m11, win[du + 1][dv + 1] + w);
            }
            g_p1[(b * 6 + 3 * cg + cc) * 224 + i * 16 + j] =
                0.25f * ((m00 + m01) + (m10 + m11));
        }
    }
}

// ---------------------------------------------------------------------------
// Kernel B: max-plus conv2 (C=6 -> O=16, k=5) + 2x2 avgpool.
// grid (2, B): CTA = 8 output channels of one image. 224 threads, 200 active:
// thread = (ocp 0..7, sp 0..24). p1 rows padded to 16 floats -> LDS.64 windows.
// ---------------------------------------------------------------------------
__global__ void __launch_bounds__(224)
conv2_kernel(const float* __restrict__ w2)
{
    const int og = blockIdx.x, b = blockIdx.y;   // out channels og*8 .. og*8+7
    const int tid = threadIdx.x;

    __shared__ __align__(16) float p1s[6 * 14 * 16];  // 1344
    __shared__ __align__(16) float ws[8 * 6 * 28];    // 1344 (filters padded)

    const float* p1b = g_p1 + b * 1344;
    for (int i = tid; i < 1344; i += 224) p1s[i] = p1b[i];
    for (int i = tid; i < 1200; i += 224) {
        int f = i / 25, t = i % 25;
        ws[f * 28 + t] = w2[og * 1200 + i];
    }
    __syncthreads();

    if (tid < 200) {
        const int ocp = tid / 25, sp = tid % 25;
        const int i = sp / 5, j = sp % 5;
        const int wbase = ocp * 6 * 28;
        const int pbase = i * 32 + 2 * j;        // (2i)*16 + 2j, even

        float acc = 0.0f;
        #pragma unroll 1
        for (int c = 0; c < 6; c++) {
            float win[6][6];
            #pragma unroll
            for (int u = 0; u < 6; u++) {
                const float2* r = (const float2*)&p1s[c * 224 + pbase + u * 16];
                float2 a = r[0], bb = r[1], c2 = r[2];
                win[u][0] = a.x;  win[u][1] = a.y;
                win[u][2] = bb.x; win[u][3] = bb.y;
                win[u][4] = c2.x; win[u][5] = c2.y;
            }

            float wr[25];
            {
                const float4* wq = (const float4*)&ws[wbase + c * 28];
                #pragma unroll
                for (int q = 0; q < 6; q++) {
                    float4 v = wq[q];
                    wr[4 * q]     = v.x; wr[4 * q + 1] = v.y;
                    wr[4 * q + 2] = v.z; wr[4 * q + 3] = v.w;
                }
                wr[24] = ws[wbase + c * 28 + 24];
            }

            float m00 = win[0][0] + wr[0];
            float m01 = win[0][1] + wr[0];
            float m10 = win[1][0] + wr[0];
            float m11 = win[1][1] + wr[0];
            #pragma unroll
            for (int t = 1; t < 25; t++) {
                const int du = t / 5, dv = t % 5;
                const float w = wr[t];
                m00 = fmaxf(m00, win[du][dv]         + w);
                m01 = fmaxf(m01, win[du][dv + 1]     + w);
                m10 = fmaxf(m10, win[du + 1][dv]     + w);
                m11 = fmaxf(m11, win[du + 1][dv + 1] + w);
            }
            acc += (m00 + m01) + (m10 + m11);
        }
        g_p2[b * 400 + (og * 8 + ocp) * 25 + sp] = 0.25f * acc;
    }
}

// ---------------------------------------------------------------------------
// Kernel C: FC stack. grid B/2, 512 threads (16 warps), 2 images per CTA.
// float4 loads throughout; warp computes 2 outputs per task.
// ---------------------------------------------------------------------------
__global__ void __launch_bounds__(512)
fc_kernel(const float* __restrict__ fw1, const float* __restrict__ fb1,
          const float* __restrict__ fw2, const float* __restrict__ fb2,
          const float* __restrict__ fw3, const float* __restrict__ fb3,
          float* __restrict__ out)
{
    const int bg = blockIdx.x;
    const int tid = threadIdx.x;
    const int warp = tid >> 5, lane = tid & 31;

    __shared__ __align__(16) float x[2][400];
    __shared__ __align__(16) float h1[2][120];
    __shared__ __align__(16) float h2[2][84];

    for (int i = tid; i < 800; i += 512)
        x[i / 400][i % 400] = g_p2[bg * 800 + i];
    __syncthreads();

    // fc1: 400 -> 120, relu. 120 tasks = (img, out-pair).
    for (int t = warp; t < 120; t += 16) {
        const int img = t & 1, oo = t >> 1;
        const int o0 = 2 * oo, o1 = o0 + 1;
        const float4* wa = (const float4*)(fw1 + o0 * 400);
        const float4* wb = (const float4*)(fw1 + o1 * 400);
        const float4* xv = (const float4*)x[img];
        float sa = 0.0f, sb = 0.0f;
        #pragma unroll
        for (int k = 0; k < 3; k++) {
            const int i4 = lane + 32 * k;
            float4 v = xv[i4], a = wa[i4], c = wb[i4];
            sa = fmaf(v.x, a.x, sa); sa = fmaf(v.y, a.y, sa);
            sa = fmaf(v.z, a.z, sa); sa = fmaf(v.w, a.w, sa);
            sb = fmaf(v.x, c.x, sb); sb = fmaf(v.y, c.y, sb);
            sb = fmaf(v.z, c.z, sb); sb = fmaf(v.w, c.w, sb);
        }
        if (lane < 4) {
            const int i4 = 96 + lane;
            float4 v = xv[i4], a = wa[i4], c = wb[i4];
            sa = fmaf(v.x, a.x, sa); sa = fmaf(v.y, a.y, sa);
            sa = fmaf(v.z, a.z, sa); sa = fmaf(v.w, a.w, sa);
            sb = fmaf(v.x, c.x, sb); sb = fmaf(v.y, c.y, sb);
            sb = fmaf(v.z, c.z, sb); sb = fmaf(v.w, c.w, sb);
        }
        #pragma unroll
        for (int off = 16; off; off >>= 1) {
            sa += __shfl_xor_sync(0xffffffffu, sa, off);
            sb += __shfl_xor_sync(0xffffffffu, sb, off);
        }
        if (lane == 0) {
            h1[img][o0] = fmaxf(sa + fb1[o0], 0.0f);
            h1[img][o1] = fmaxf(sb + fb1[o1], 0.0f);
        }
    }
    __syncthreads();

    // fc2: 120 -> 84, relu. 84 tasks; 30 float4 per row, lanes 0..29.
    for (int t = warp; t < 84; t += 16) {
        const int img = t & 1, oo = t >> 1;
        const int o0 = 2 * oo, o1 = o0 + 1;
        const float4* wa = (const float4*)(fw2 + o0 * 120);
        const float4* wb = (const float4*)(fw2 + o1 * 120);
        const float4* xv = (const float4*)h1[img];
        float sa = 0.0f, sb = 0.0f;
        if (lane < 30) {
            float4 v = xv[lane], a = wa[lane], c = wb[lane];
            sa = fmaf(v.x, a.x, sa); sa = fmaf(v.y, a.y, sa);
            sa = fmaf(v.z, a.z, sa); sa = fmaf(v.w, a.w, sa);
            sb = fmaf(v.x, c.x, sb); sb = fmaf(v.y, c.y, sb);
            sb = fmaf(v.z, c.z, sb); sb = fmaf(v.w, c.w, sb);
        }
        #pragma unroll
        for (int off = 16; off; off >>= 1) {
            sa += __shfl_xor_sync(0xffffffffu, sa, off);
            sb += __shfl_xor_sync(0xffffffffu, sb, off);
        }
        if (lane == 0) {
            h2[img][o0] = fmaxf(sa + fb2[o0], 0.0f);
            h2[img][o1] = fmaxf(sb + fb2[o1], 0.0f);
        }
    }
    __syncthreads();

    // fc3: 84 -> 10. 20 tasks = (img, out); 21 float4 per row, lanes 0..20.
    for (int t = warp; t < 20; t += 16) {
        const int img = t & 1, o = t >> 1;
        const float4* wr = (const float4*)(fw3 + o * 84);
        const float4* xv = (const float4*)h2[img];
        float s = 0.0f;
        if (lane < 21) {
            float4 v = xv[lane], a = wr[lane];
            s = fmaf(v.x, a.x, s); s = fmaf(v.y, a.y, s);
            s = fmaf(v.z, a.z, s); s = fmaf(v.w, a.w, s);
        }
        #pragma unroll
        for (int off = 16; off; off >>= 1) s += __shfl_xor_sync(0xffffffffu, s, off);
        if (lane == 0) out[(2 * bg + img) * 10 + o] = s + fb3[o];
    }
}

extern "C" void kernel_launch(void* const* d_in, const int* in_sizes, int n_in,
                              void* d_out, int out_size)
{
    const float* input = (const float*)d_in[0];
    const float* w1    = (const float*)d_in[1];
    const float* w2    = (const float*)d_in[2];
    const float* fw1   = (const float*)d_in[3];
    const float* fb1   = (const float*)d_in[4];
    const float* fw2   = (const float*)d_in[5];
    const float* fb2   = (const float*)d_in[6];
    const float* fw3   = (const float*)d_in[7];
    const float* fb3   = (const float*)d_in[8];

    const int B = in_sizes[0] / 784;  // 256

    conv1_kernel<<<dim3(2, B), 224>>>(input, w1);
    conv2_kernel<<<dim3(2, B), 224>>>(w2);
    fc_kernel<<<B / 2, 512>>>(fw1, fb1, fw2, fb2, fw3, fb3, (float*)d_out);
}